// round 15
// baseline (speedup 1.0000x reference)
#include <cuda_runtime.h>
#include <cuda_bf16.h>
#include <math.h>
#include <stdint.h>

// Problem constants
#define BB 2
#define TT 2048
#define DM 2048
#define NH 32
#define NKV 8
#define HD 64
#define MROWS (BB*TT)          // 4096

// ---------------------------------------------------------------------------
// Scratch (device globals — no allocation allowed)
// ---------------------------------------------------------------------------
__device__ float g_qkv[MROWS * 3072];       // fused Q|K|V fp32

// split-bf16 operand buffers
__device__ __align__(16) __nv_bfloat16 g_xh[MROWS * DM];
__device__ __align__(16) __nv_bfloat16 g_xl[MROWS * DM];
__device__ __align__(16) __nv_bfloat16 g_wqkvh[3072 * DM];
__device__ __align__(16) __nv_bfloat16 g_wqkvl[3072 * DM];
__device__ __align__(16) __nv_bfloat16 g_woh[DM * NH*HD];
__device__ __align__(16) __nv_bfloat16 g_wol[DM * NH*HD];
__device__ __align__(16) __nv_bfloat16 g_ah[MROWS * NH*HD];
__device__ __align__(16) __nv_bfloat16 g_al[MROWS * NH*HD];

// split bf16 q/k/v for attention (post-rope, compact layouts)
__device__ __align__(16) __nv_bfloat16 g_qsh[MROWS * NH * HD];
__device__ __align__(16) __nv_bfloat16 g_qsl[MROWS * NH * HD];
__device__ __align__(16) __nv_bfloat16 g_ksh[MROWS * NKV * HD];
__device__ __align__(16) __nv_bfloat16 g_ksl[MROWS * NKV * HD];
__device__ __align__(16) __nv_bfloat16 g_vsh[MROWS * NKV * HD];
__device__ __align__(16) __nv_bfloat16 g_vsl[MROWS * NKV * HD];

// ---------------------------------------------------------------------------
// mma.sync / cp.async helpers (target-portable)
// ---------------------------------------------------------------------------
__device__ __forceinline__ uint32_t smem_u32(const void* p) {
    uint32_t a;
    asm("{ .reg .u64 t; cvta.to.shared.u64 t, %1; cvt.u32.u64 %0, t; }" : "=r"(a) : "l"(p));
    return a;
}
__device__ __forceinline__ void ldsm_x4(uint32_t* r, uint32_t addr) {
    asm volatile("ldmatrix.sync.aligned.m8n8.x4.shared.b16 {%0,%1,%2,%3}, [%4];"
        : "=r"(r[0]), "=r"(r[1]), "=r"(r[2]), "=r"(r[3]) : "r"(addr));
}
__device__ __forceinline__ void ldsm_x4t(uint32_t* r, uint32_t addr) {
    asm volatile("ldmatrix.sync.aligned.m8n8.x4.trans.shared.b16 {%0,%1,%2,%3}, [%4];"
        : "=r"(r[0]), "=r"(r[1]), "=r"(r[2]), "=r"(r[3]) : "r"(addr));
}
__device__ __forceinline__ void mma16816(float* d, const uint32_t* a, const uint32_t* b) {
    asm volatile("mma.sync.aligned.m16n8k16.row.col.f32.bf16.bf16.f32 "
        "{%0,%1,%2,%3}, {%4,%5,%6,%7}, {%8,%9}, {%0,%1,%2,%3};"
        : "+f"(d[0]), "+f"(d[1]), "+f"(d[2]), "+f"(d[3])
        : "r"(a[0]), "r"(a[1]), "r"(a[2]), "r"(a[3]), "r"(b[0]), "r"(b[1]));
}
__device__ __forceinline__ void cp16(uint32_t dst, const void* src) {
    asm volatile("cp.async.cg.shared.global [%0], [%1], 16;" :: "r"(dst), "l"(src) : "memory");
}
#define CP_COMMIT() asm volatile("cp.async.commit_group;" ::: "memory")
#define CP_WAIT1()  asm volatile("cp.async.wait_group 1;" ::: "memory")
#define CP_WAIT0()  asm volatile("cp.async.wait_group 0;" ::: "memory")

// fast bf16x2 pack (single F2FP) + hi-reconstruct by bit shift
__device__ __forceinline__ uint32_t packbf2(float x, float y) {
    __nv_bfloat162 t = __floats2bfloat162_rn(x, y);
    return *(uint32_t*)&t;
}
__device__ __forceinline__ void split_pack(float x, float y, uint32_t& hi, uint32_t& lo) {
    hi = packbf2(x, y);
    float hx = __uint_as_float(hi << 16);           // bf16 -> f32 is <<16
    float hy = __uint_as_float(hi & 0xFFFF0000u);
    lo = packbf2(x - hx, y - hy);
}

// ---------------------------------------------------------------------------
// Fused split conversion for all 5 inputs (x, Wq, Wk, Wv, Wo) in ONE launch.
// ---------------------------------------------------------------------------
#define CVT_N0 (MROWS*DM)                 // x        : 8388608
#define CVT_N1 (CVT_N0 + NH*HD*DM)        // +Wq      : 12582912
#define CVT_N2 (CVT_N1 + NKV*HD*DM)       // +Wk      : 13631488
#define CVT_N3 (CVT_N2 + NKV*HD*DM)       // +Wv      : 14680064
#define CVT_N4 (CVT_N3 + DM*NH*HD)        // +Wo      : 18874368

__global__ void cvt_split5(
    const float* __restrict__ x,  const float* __restrict__ wq,
    const float* __restrict__ wk, const float* __restrict__ wv,
    const float* __restrict__ wo,
    __nv_bfloat16* __restrict__ xh,    __nv_bfloat16* __restrict__ xl,
    __nv_bfloat16* __restrict__ wqkvh, __nv_bfloat16* __restrict__ wqkvl,
    __nv_bfloat16* __restrict__ woh,   __nv_bfloat16* __restrict__ wol)
{
    int i = blockIdx.x * blockDim.x + threadIdx.x;
    if (i >= CVT_N4) return;
    const float* src; __nv_bfloat16 *dh, *dl; int j;
    if (i < CVT_N0)      { j = i;          src = x;  dh = xh;    dl = xl; }
    else if (i < CVT_N1) { j = i - CVT_N0; src = wq; dh = wqkvh; dl = wqkvl; }
    else if (i < CVT_N2) { j = i - CVT_N1; src = wk; dh = wqkvh + (size_t)2048*DM; dl = wqkvl + (size_t)2048*DM; }
    else if (i < CVT_N3) { j = i - CVT_N2; src = wv; dh = wqkvh + (size_t)2560*DM; dl = wqkvl + (size_t)2560*DM; }
    else                 { j = i - CVT_N3; src = wo; dh = woh;   dl = wol; }
    float f = src[j];
    __nv_bfloat16 h = __float2bfloat16(f);
    float r = f - __bfloat162float(h);
    dh[j] = h;
    dl[j] = __float2bfloat16(r);
}

// ---------------------------------------------------------------------------
// Fused RoPE(q)+RoPE(k)+split(v) in ONE launch, reading the fused QKV buffer.
// ---------------------------------------------------------------------------
#define PRE_TQ (MROWS*NH*32)              // 4194304
#define PRE_TK (PRE_TQ + MROWS*NKV*32)    // 5242880
#define PRE_TV (PRE_TK + MROWS*NKV*HD)    // 7340032

__global__ void prep_attn(
    const float* __restrict__ qkv,
    const float* __restrict__ cost, const float* __restrict__ sint,
    __nv_bfloat16* __restrict__ qsh, __nv_bfloat16* __restrict__ qsl,
    __nv_bfloat16* __restrict__ ksh, __nv_bfloat16* __restrict__ ksl,
    __nv_bfloat16* __restrict__ vsh, __nv_bfloat16* __restrict__ vsl)
{
    int i = blockIdx.x * blockDim.x + threadIdx.x;
    if (i >= PRE_TV) return;

    if (i < PRE_TK) {
        // RoPE regions
        const float* src; __nv_bfloat16 *dh, *dl;
        int nh, idx; float scale;
        if (i < PRE_TQ) { idx = i;          src = qkv;        nh = NH;  scale = 0.18033688f; dh = qsh; dl = qsl; }
        else            { idx = i - PRE_TQ; src = qkv + 2048; nh = NKV; scale = 1.0f;        dh = ksh; dl = ksl; }
        int d  = idx & 31;
        int rh = idx >> 5;
        int bt = rh / nh;
        int h  = rh - bt * nh;
        int t  = bt & (TT - 1);
        float c = cost[t * HD + d];
        float s = sint[t * HD + d];
        const float* base = src + (size_t)bt * 3072 + h * HD;
        float x1 = base[d];
        float x2 = base[d + 32];
        float y1 = fmaf(x1, c, -x2 * s) * scale;
        float y2 = fmaf(x2, c,  x1 * s) * scale;
        size_t o = (size_t)rh * HD;
        __nv_bfloat16 h1 = __float2bfloat16(y1);
        __nv_bfloat16 h2 = __float2bfloat16(y2);
        dh[o + d]      = h1;
        dh[o + d + 32] = h2;
        dl[o + d]      = __float2bfloat16(y1 - __bfloat162float(h1));
        dl[o + d + 32] = __float2bfloat16(y2 - __bfloat162float(h2));
    } else {
        // V split (cols 2560..3071 of fused QKV)
        int j   = i - PRE_TK;
        int row = j >> 9;            // NKV*HD = 512
        int c   = j & 511;
        float f = qkv[(size_t)row * 3072 + 2560 + c];
        __nv_bfloat16 h = __float2bfloat16(f);
        float r = f - __bfloat162float(h);
        vsh[j] = h;
        vsl[j] = __float2bfloat16(r);
    }
}

// ---------------------------------------------------------------------------
// Pipelined tensor-core split-bf16 GEMM (NT); B operands via x4 ldmatrix.
// ---------------------------------------------------------------------------
#define GBM 128
#define GBN 128
#define GBK 32
#define LDS 40
#define TILE_B (GBM * LDS * 2)
#define OFF_AH 0
#define OFF_AL (TILE_B)
#define OFF_BH (2*TILE_B)
#define OFF_BL (3*TILE_B)
#define STAGE_B (4*TILE_B)
#define GEMM_SMEM (2*STAGE_B)

__global__ __launch_bounds__(256) void gemm_tc(
    const __nv_bfloat16* __restrict__ Ahg, const __nv_bfloat16* __restrict__ Alg,
    const __nv_bfloat16* __restrict__ Bhg, const __nv_bfloat16* __restrict__ Blg,
    float* __restrict__ C, int M, int N, int K)
{
    extern __shared__ char smem[];
    const uint32_t sb = smem_u32(smem);

    const int tid  = threadIdx.x;
    const int wid  = tid >> 5;
    const int lane = tid & 31;
    const int wm   = wid & 1;
    const int wn   = wid >> 1;

    const int brow = blockIdx.y * GBM;
    const int bcol = blockIdx.x * GBN;

    const uint32_t aoff = (uint32_t)((wm*64 + (lane & 15)) * (LDS*2) + (lane >> 4) * 16);
    // x4 B-fragment base: 16 n-rows per load
    const uint32_t bx4  = (uint32_t)((wn*32 + (lane & 15)) * (LDS*2) + (lane >> 4) * 16);

    const int lr  = tid >> 2;
    const int lc8 = tid & 3;

    float acc[4][4][4];
    #pragma unroll
    for (int mi = 0; mi < 4; mi++)
        #pragma unroll
        for (int ni = 0; ni < 4; ni++)
            #pragma unroll
            for (int r = 0; r < 4; r++) acc[mi][ni][r] = 0.f;

    const int niter = K / GBK;

    auto load_stage = [&](int stage, int k0) {
        const uint32_t st = sb + stage * STAGE_B;
        #pragma unroll
        for (int i = 0; i < 2; i++) {
            int r = lr + i * 64;
            size_t ga = (size_t)(brow + r) * K + k0 + lc8 * 8;
            size_t gb = (size_t)(bcol + r) * K + k0 + lc8 * 8;
            uint32_t so = (uint32_t)(r * (LDS*2) + lc8 * 16);
            cp16(st + OFF_AH + so, Ahg + ga);
            cp16(st + OFF_AL + so, Alg + ga);
            cp16(st + OFF_BH + so, Bhg + gb);
            cp16(st + OFF_BL + so, Blg + gb);
        }
    };

    load_stage(0, 0);
    CP_COMMIT();

    for (int it = 0; it < niter; it++) {
        const int buf = it & 1;
        if (it + 1 < niter) {
            load_stage(buf ^ 1, (it + 1) * GBK);
            CP_COMMIT();
            CP_WAIT1();
        } else {
            CP_WAIT0();
        }
        __syncthreads();

        const uint32_t st = sb + buf * STAGE_B;
        #pragma unroll
        for (int kk = 0; kk < GBK; kk += 16) {
            const uint32_t kb = kk * 2;

            uint32_t ah[4][4], bh[4][2];
            #pragma unroll
            for (int mi = 0; mi < 4; mi++)
                ldsm_x4(ah[mi], st + OFF_AH + aoff + mi * 16 * (LDS*2) + kb);
            #pragma unroll
            for (int np = 0; np < 2; np++) {
                uint32_t t[4];
                ldsm_x4(t, st + OFF_BH + bx4 + np * 16 * (LDS*2) + kb);
                bh[2*np][0]   = t[0]; bh[2*np][1]   = t[2];
                bh[2*np+1][0] = t[1]; bh[2*np+1][1] = t[3];
            }

            #pragma unroll
            for (int mi = 0; mi < 4; mi++)
                #pragma unroll
                for (int ni = 0; ni < 4; ni++)
                    mma16816(acc[mi][ni], ah[mi], bh[ni]);

            {
                uint32_t bl[4][2];
                #pragma unroll
                for (int np = 0; np < 2; np++) {
                    uint32_t t[4];
                    ldsm_x4(t, st + OFF_BL + bx4 + np * 16 * (LDS*2) + kb);
                    bl[2*np][0]   = t[0]; bl[2*np][1]   = t[2];
                    bl[2*np+1][0] = t[1]; bl[2*np+1][1] = t[3];
                }
                #pragma unroll
                for (int mi = 0; mi < 4; mi++)
                    #pragma unroll
                    for (int ni = 0; ni < 4; ni++)
                        mma16816(acc[mi][ni], ah[mi], bl[ni]);
            }
            {
                uint32_t al[4][4];
                #pragma unroll
                for (int mi = 0; mi < 4; mi++)
                    ldsm_x4(al[mi], st + OFF_AL + aoff + mi * 16 * (LDS*2) + kb);
                #pragma unroll
                for (int mi = 0; mi < 4; mi++)
                    #pragma unroll
                    for (int ni = 0; ni < 4; ni++)
                        mma16816(acc[mi][ni], al[mi], bh[ni]);
            }
        }
        __syncthreads();
    }

    const int er = lane >> 2;
    const int ec = (lane & 3) * 2;
    #pragma unroll
    for (int mi = 0; mi < 4; mi++) {
        #pragma unroll
        for (int ni = 0; ni < 4; ni++) {
            int row = brow + wm*64 + mi*16 + er;
            int col = bcol + wn*32 + ni*8 + ec;
            float2* p0 = (float2*)(C + (size_t)row * N + col);
            float2* p1 = (float2*)(C + (size_t)(row + 8) * N + col);
            *p0 = make_float2(acc[mi][ni][0], acc[mi][ni][1]);
            *p1 = make_float2(acc[mi][ni][2], acc[mi][ni][3]);
        }
    }
}

// ---------------------------------------------------------------------------
// Flash attention: GQA-paired + LPT; interleaved accumulator chains.
// ---------------------------------------------------------------------------
#define ATQ 64
#define ATK 64
#define ASTRB  144       // 72 bf16 per row (64 data + 8 pad)
#define SQ_SZ    18432   // QH+QL per head
#define SST_BASE 36864
#define SST_SZ   36864   // per stage: KH,KL,VH,VL each 9216
#define SK_H 0
#define SK_L 9216
#define SV_H 18432
#define SV_L 27648
#define ATTN_SMEM (SST_BASE + 2*SST_SZ)   // 110592 B

__global__ __launch_bounds__(256) void attn_tc(
    const __nv_bfloat16* __restrict__ qsh, const __nv_bfloat16* __restrict__ qsl,
    const __nv_bfloat16* __restrict__ ksh, const __nv_bfloat16* __restrict__ ksl,
    const __nv_bfloat16* __restrict__ vsh, const __nv_bfloat16* __restrict__ vsl,
    __nv_bfloat16* __restrict__ Ohg, __nv_bfloat16* __restrict__ Olg)
{
    extern __shared__ char smem[];
    const uint32_t sb = smem_u32(smem);
    const int tid  = threadIdx.x;
    const int wid  = tid >> 5;        // 0..7
    const int lane = tid & 31;
    const int half = wid >> 2;        // 0/1 -> which q-head
    const int wih  = wid & 3;         // warp-in-half

    // LPT: heaviest (largest qt) CTAs launch first
    const int qt = (int)gridDim.x - 1 - (int)blockIdx.x;
    const int y  = blockIdx.y;        // b*(NKV*2) + kv*2 + ph
    const int b  = y >> 4;
    const int kv = (y >> 1) & 7;
    const int ph = y & 1;
    const int h  = kv * 4 + ph * 2 + half;
    const int q0 = qt * ATQ;
    const int ntiles = qt + 1;

    auto load_kv = [&](int stage, int k0) {
        const uint32_t st = sb + SST_BASE + stage * SST_SZ;
        #pragma unroll
        for (int i = 0; i < 2; i++) {
            int idx = tid + i * 256;
            int r   = idx >> 3;
            int c8  = idx & 7;
            size_t g = ((size_t)(b * TT + k0 + r) * NKV + kv) * HD + c8 * 8;
            uint32_t so = (uint32_t)(r * ASTRB + c8 * 16);
            cp16(st + SK_H + so, ksh + g);
            cp16(st + SK_L + so, ksl + g);
            cp16(st + SV_H + so, vsh + g);
            cp16(st + SV_L + so, vsl + g);
        }
    };

    // ---- load both Q tiles ----
    {
        const int tl = tid & 127;
        const uint32_t qbase = (uint32_t)((tid >> 7) * SQ_SZ);
        #pragma unroll
        for (int i = 0; i < 4; i++) {
            int idx = tl + i * 128;
            int r   = idx >> 3;
            int c8  = idx & 7;
            size_t g = ((size_t)(b * TT + q0 + r) * NH + h) * HD + c8 * 8;
            uint32_t so = qbase + (uint32_t)(r * ASTRB + c8 * 16);
            *(uint4*)(smem + so) = *(const uint4*)(qsh + g);
            *(uint4*)(smem + so + 9216) = *(const uint4*)(qsl + g);
        }
    }

    load_kv(0, 0);
    CP_COMMIT();

    __syncthreads();

    // ---- per-warp Q fragments ----
    uint32_t qh[4][4], ql[4][4];
    {
        uint32_t abase = (uint32_t)(half * SQ_SZ + (wih*16 + (lane & 15)) * ASTRB + (lane >> 4) * 16);
        #pragma unroll
        for (int ks = 0; ks < 4; ks++) {
            ldsm_x4(qh[ks], sb + abase + ks * 32);
            ldsm_x4(ql[ks], sb + abase + 9216 + ks * 32);
        }
    }

    float o[8][4];
    #pragma unroll
    for (int dt = 0; dt < 8; dt++)
        #pragma unroll
        for (int r = 0; r < 4; r++) o[dt][r] = 0.f;
    float m0 = -1e30f, m1 = -1e30f, l0 = 0.f, l1 = 0.f;

    const uint32_t fb = (uint32_t)((lane & 15) * ASTRB + (lane >> 4) * 16);

    for (int kt = 0; kt < ntiles; kt++) {
        const int k0 = kt * ATK;
        if (kt + 1 < ntiles) {
            load_kv((kt + 1) & 1, k0 + ATK);
            CP_COMMIT();
            CP_WAIT1();
        } else {
            CP_WAIT0();
        }
        __syncthreads();

        const uint32_t st = sb + SST_BASE + (kt & 1) * SST_SZ;

        // ---- S = Q K^T (split 3-pass, interleaved accumulator chains) ----
        float s[8][4];
        #pragma unroll
        for (int nt = 0; nt < 8; nt++)
            #pragma unroll
            for (int r = 0; r < 4; r++) s[nt][r] = 0.f;

        #pragma unroll
        for (int ks = 0; ks < 4; ks++) {
            #pragma unroll
            for (int np = 0; np < 4; np++) {
                uint32_t th[4], tl4[4];
                uint32_t ka = st + fb + np * (16 * ASTRB) + ks * 32;
                ldsm_x4(th,  SK_H + ka);
                ldsm_x4(tl4, SK_L + ka);
                uint32_t bh0[2] = {th[0], th[2]}, bh1[2] = {th[1], th[3]};
                uint32_t bl0[2] = {tl4[0], tl4[2]}, bl1[2] = {tl4[1], tl4[3]};
                mma16816(s[2*np],   qh[ks], bh0);
                mma16816(s[2*np+1], qh[ks], bh1);
                mma16816(s[2*np],   qh[ks], bl0);
                mma16816(s[2*np+1], qh[ks], bl1);
                mma16816(s[2*np],   ql[ks], bh0);
                mma16816(s[2*np+1], ql[ks], bh1);
            }
        }

        // ---- causal mask (diagonal tile only) ----
        const int row0 = q0 + wih * 16 + (lane >> 2);
        const int row1 = row0 + 8;
        if (kt == qt) {
            #pragma unroll
            for (int nt = 0; nt < 8; nt++) {
                int col = k0 + nt * 8 + (lane & 3) * 2;
                if (col     > row0) s[nt][0] = -1e30f;
                if (col + 1 > row0) s[nt][1] = -1e30f;
                if (col     > row1) s[nt][2] = -1e30f;
                if (col + 1 > row1) s[nt][3] = -1e30f;
            }
        }

        // ---- online softmax (exp2 domain) ----
        float mx0 = m0, mx1 = m1;
        #pragma unroll
        for (int nt = 0; nt < 8; nt++) {
            mx0 = fmaxf(mx0, fmaxf(s[nt][0], s[nt][1]));
            mx1 = fmaxf(mx1, fmaxf(s[nt][2], s[nt][3]));
        }
        mx0 = fmaxf(mx0, __shfl_xor_sync(0xFFFFFFFF, mx0, 1));
        mx0 = fmaxf(mx0, __shfl_xor_sync(0xFFFFFFFF, mx0, 2));
        mx1 = fmaxf(mx1, __shfl_xor_sync(0xFFFFFFFF, mx1, 1));
        mx1 = fmaxf(mx1, __shfl_xor_sync(0xFFFFFFFF, mx1, 2));

        float c0 = exp2f(m0 - mx0);
        float c1 = exp2f(m1 - mx1);
        m0 = mx0; m1 = mx1;
        l0 *= c0;  l1 *= c1;
        #pragma unroll
        for (int dt = 0; dt < 8; dt++) {
            o[dt][0] *= c0; o[dt][1] *= c0;
            o[dt][2] *= c1; o[dt][3] *= c1;
        }

        // ---- P = exp2(S - m), pack split A-fragments ----
        uint32_t pha[4][4], pla[4][4];
        float rs0 = 0.f, rs1 = 0.f;
        #pragma unroll
        for (int j = 0; j < 8; j++) {
            float p0 = exp2f(s[j][0] - m0);
            float p1 = exp2f(s[j][1] - m0);
            float p2 = exp2f(s[j][2] - m1);
            float p3 = exp2f(s[j][3] - m1);
            rs0 += p0 + p1;
            rs1 += p2 + p3;
            uint32_t hi01, lo01, hi23, lo23;
            split_pack(p0, p1, hi01, lo01);
            split_pack(p2, p3, hi23, lo23);
            int c = j >> 1;
            if ((j & 1) == 0) {
                pha[c][0] = hi01; pla[c][0] = lo01;
                pha[c][1] = hi23; pla[c][1] = lo23;
            } else {
                pha[c][2] = hi01; pla[c][2] = lo01;
                pha[c][3] = hi23; pla[c][3] = lo23;
            }
        }
        rs0 += __shfl_xor_sync(0xFFFFFFFF, rs0, 1);
        rs0 += __shfl_xor_sync(0xFFFFFFFF, rs0, 2);
        rs1 += __shfl_xor_sync(0xFFFFFFFF, rs1, 1);
        rs1 += __shfl_xor_sync(0xFFFFFFFF, rs1, 2);
        l0 += rs0;
        l1 += rs1;

        // ---- O += P V (x4 trans loads; interleaved chains) ----
        #pragma unroll
        for (int ks = 0; ks < 4; ks++) {
            #pragma unroll
            for (int dp = 0; dp < 4; dp++) {
                uint32_t vh4[4], vl4[4];
                uint32_t va = st + fb + ks * (16 * ASTRB) + dp * 32;
                ldsm_x4t(vh4, SV_H + va);
                ldsm_x4t(vl4, SV_L + va);
                uint32_t b0h[2] = {vh4[0], vh4[1]}, b1h[2] = {vh4[2], vh4[3]};
                uint32_t b0l[2] = {vl4[0], vl4[1]}, b1l[2] = {vl4[2], vl4[3]};
                mma16816(o[2*dp],   pha[ks], b0h);
                mma16816(o[2*dp+1], pha[ks], b1h);
                mma16816(o[2*dp],   pha[ks], b0l);
                mma16816(o[2*dp+1], pha[ks], b1l);
                mma16816(o[2*dp],   pla[ks], b0h);
                mma16816(o[2*dp+1], pla[ks], b1h);
            }
        }
        __syncthreads();
    }

    // ---- finalize & write split output ----
    const float i0 = 1.f / l0;
    const float i1 = 1.f / l1;
    const int row0 = q0 + wih * 16 + (lane >> 2);
    const int row1 = row0 + 8;
    const int colb = h * HD + (lane & 3) * 2;
    #pragma unroll
    for (int dt = 0; dt < 8; dt++) {
        int col = colb + dt * 8;
        uint32_t hi0, lo0, hi1, lo1;
        split_pack(o[dt][0] * i0, o[dt][1] * i0, hi0, lo0);
        split_pack(o[dt][2] * i1, o[dt][3] * i1, hi1, lo1);
        size_t g0 = (size_t)(b * TT + row0) * (NH * HD) + col;
        size_t g1 = (size_t)(b * TT + row1) * (NH * HD) + col;
        *(uint32_t*)(Ohg + g0) = hi0;
        *(uint32_t*)(Olg + g0) = lo0;
        *(uint32_t*)(Ohg + g1) = hi1;
        *(uint32_t*)(Olg + g1) = lo1;
    }
}

// ---------------------------------------------------------------------------
// Launch
// ---------------------------------------------------------------------------
extern "C" void kernel_launch(void* const* d_in, const int* in_sizes, int n_in,
                              void* d_out, int out_size)
{
    const float* x    = (const float*)d_in[0];
    const float* cosv = (const float*)d_in[1];
    const float* sinv = (const float*)d_in[2];
    const float* Wq   = (const float*)d_in[3];
    const float* Wk   = (const float*)d_in[4];
    const float* Wv   = (const float*)d_in[5];
    const float* Wo   = (const float*)d_in[6];
    float* out = (float*)d_out;

    float *qkv;
    cudaGetSymbolAddress((void**)&qkv, g_qkv);

    __nv_bfloat16 *xh, *xl, *wqkvh, *wqkvl, *woh, *wol, *ah, *al;
    __nv_bfloat16 *qsh, *qsl, *ksh, *ksl, *vsh, *vsl;
    cudaGetSymbolAddress((void**)&xh,    g_xh);     cudaGetSymbolAddress((void**)&xl,    g_xl);
    cudaGetSymbolAddress((void**)&wqkvh, g_wqkvh);  cudaGetSymbolAddress((void**)&wqkvl, g_wqkvl);
    cudaGetSymbolAddress((void**)&woh,   g_woh);    cudaGetSymbolAddress((void**)&wol,   g_wol);
    cudaGetSymbolAddress((void**)&ah,    g_ah);     cudaGetSymbolAddress((void**)&al,    g_al);
    cudaGetSymbolAddress((void**)&qsh,   g_qsh);    cudaGetSymbolAddress((void**)&qsl,   g_qsl);
    cudaGetSymbolAddress((void**)&ksh,   g_ksh);    cudaGetSymbolAddress((void**)&ksl,   g_ksl);
    cudaGetSymbolAddress((void**)&vsh,   g_vsh);    cudaGetSymbolAddress((void**)&vsl,   g_vsl);

    cudaFuncSetAttribute(gemm_tc, cudaFuncAttributeMaxDynamicSharedMemorySize, GEMM_SMEM);
    cudaFuncSetAttribute(attn_tc, cudaFuncAttributeMaxDynamicSharedMemorySize, ATTN_SMEM);

    // all split conversions in one launch
    cvt_split5<<<(CVT_N4 + 255)/256, 256>>>(x, Wq, Wk, Wv, Wo,
                                            xh, xl, wqkvh, wqkvl, woh, wol);

    // fused Q|K|V projection (N=3072)
    gemm_tc<<<dim3(3072/GBN, MROWS/GBM), 256, GEMM_SMEM>>>(xh, xl, wqkvh, wqkvl, qkv, MROWS, 3072, DM);

    // RoPE(q,k) + split(v) in one launch; q pre-scaled by (1/8)*log2(e)
    prep_attn<<<(PRE_TV + 255)/256, 256>>>(qkv, cosv, sinv, qsh, qsl, ksh, ksl, vsh, vsl);

    // tensor-core flash attention (GQA-paired, LPT order) -> split bf16 att
    attn_tc<<<dim3(TT/ATQ, BB*NKV*2), 256, ATTN_SMEM>>>(qsh, qsl, ksh, ksl, vsh, vsl, ah, al);

    // output projection
    gemm_tc<<<dim3(DM/GBN, MROWS/GBM), 256, GEMM_SMEM>>>(ah, al, woh, wol, out, MROWS, DM, DM);
}

// round 16
// speedup vs baseline: 1.1938x; 1.1938x over previous
#include <cuda_runtime.h>
#include <cuda_bf16.h>
#include <math.h>
#include <stdint.h>

// Problem constants
#define BB 2
#define TT 2048
#define DM 2048
#define NH 32
#define NKV 8
#define HD 64
#define MROWS (BB*TT)          // 4096

// ---------------------------------------------------------------------------
// Scratch (device globals — no allocation allowed)
// ---------------------------------------------------------------------------
__device__ float g_qkv[MROWS * 3072];       // fused Q|K|V fp32

// split-bf16 operand buffers
__device__ __align__(16) __nv_bfloat16 g_xh[MROWS * DM];
__device__ __align__(16) __nv_bfloat16 g_xl[MROWS * DM];
__device__ __align__(16) __nv_bfloat16 g_wqkvh[3072 * DM];
__device__ __align__(16) __nv_bfloat16 g_wqkvl[3072 * DM];
__device__ __align__(16) __nv_bfloat16 g_woh[DM * NH*HD];
__device__ __align__(16) __nv_bfloat16 g_wol[DM * NH*HD];
__device__ __align__(16) __nv_bfloat16 g_ah[MROWS * NH*HD];
__device__ __align__(16) __nv_bfloat16 g_al[MROWS * NH*HD];

// split bf16 q/k/v for attention (post-rope, compact layouts)
__device__ __align__(16) __nv_bfloat16 g_qsh[MROWS * NH * HD];
__device__ __align__(16) __nv_bfloat16 g_qsl[MROWS * NH * HD];
__device__ __align__(16) __nv_bfloat16 g_ksh[MROWS * NKV * HD];
__device__ __align__(16) __nv_bfloat16 g_ksl[MROWS * NKV * HD];
__device__ __align__(16) __nv_bfloat16 g_vsh[MROWS * NKV * HD];
__device__ __align__(16) __nv_bfloat16 g_vsl[MROWS * NKV * HD];

// ---------------------------------------------------------------------------
// mma.sync / cp.async helpers (target-portable)
// ---------------------------------------------------------------------------
__device__ __forceinline__ uint32_t smem_u32(const void* p) {
    uint32_t a;
    asm("{ .reg .u64 t; cvta.to.shared.u64 t, %1; cvt.u32.u64 %0, t; }" : "=r"(a) : "l"(p));
    return a;
}
__device__ __forceinline__ void ldsm_x4(uint32_t* r, uint32_t addr) {
    asm volatile("ldmatrix.sync.aligned.m8n8.x4.shared.b16 {%0,%1,%2,%3}, [%4];"
        : "=r"(r[0]), "=r"(r[1]), "=r"(r[2]), "=r"(r[3]) : "r"(addr));
}
__device__ __forceinline__ void ldsm_x4t(uint32_t* r, uint32_t addr) {
    asm volatile("ldmatrix.sync.aligned.m8n8.x4.trans.shared.b16 {%0,%1,%2,%3}, [%4];"
        : "=r"(r[0]), "=r"(r[1]), "=r"(r[2]), "=r"(r[3]) : "r"(addr));
}
__device__ __forceinline__ void ldsm_x2(uint32_t* r, uint32_t addr) {
    asm volatile("ldmatrix.sync.aligned.m8n8.x2.shared.b16 {%0,%1}, [%2];"
        : "=r"(r[0]), "=r"(r[1]) : "r"(addr));
}
__device__ __forceinline__ void mma16816(float* d, const uint32_t* a, const uint32_t* b) {
    asm volatile("mma.sync.aligned.m16n8k16.row.col.f32.bf16.bf16.f32 "
        "{%0,%1,%2,%3}, {%4,%5,%6,%7}, {%8,%9}, {%0,%1,%2,%3};"
        : "+f"(d[0]), "+f"(d[1]), "+f"(d[2]), "+f"(d[3])
        : "r"(a[0]), "r"(a[1]), "r"(a[2]), "r"(a[3]), "r"(b[0]), "r"(b[1]));
}
__device__ __forceinline__ void cp16(uint32_t dst, const void* src) {
    asm volatile("cp.async.cg.shared.global [%0], [%1], 16;" :: "r"(dst), "l"(src) : "memory");
}
#define CP_COMMIT() asm volatile("cp.async.commit_group;" ::: "memory")
#define CP_WAIT1()  asm volatile("cp.async.wait_group 1;" ::: "memory")
#define CP_WAIT0()  asm volatile("cp.async.wait_group 0;" ::: "memory")

// fast bf16x2 pack (single F2FP) + hi-reconstruct by bit shift
__device__ __forceinline__ uint32_t packbf2(float x, float y) {
    __nv_bfloat162 t = __floats2bfloat162_rn(x, y);
    return *(uint32_t*)&t;
}
__device__ __forceinline__ void split_pack(float x, float y, uint32_t& hi, uint32_t& lo) {
    hi = packbf2(x, y);
    float hx = __uint_as_float(hi << 16);           // bf16 -> f32 is <<16
    float hy = __uint_as_float(hi & 0xFFFF0000u);
    lo = packbf2(x - hx, y - hy);
}

// ---------------------------------------------------------------------------
// Split-bf16 conversion: f = hi + lo
// ---------------------------------------------------------------------------
__global__ void cvt_split(const float* __restrict__ src,
                          __nv_bfloat16* __restrict__ hi,
                          __nv_bfloat16* __restrict__ lo, int n)
{
    int i = blockIdx.x * blockDim.x + threadIdx.x;
    if (i >= n) return;
    float f = src[i];
    __nv_bfloat16 h = __float2bfloat16(f);
    float r = f - __bfloat162float(h);
    hi[i] = h;
    lo[i] = __float2bfloat16(r);
}

// strided variant: pulls V columns (2560..3071) out of the fused QKV output
__global__ void cvt_splitv(const float* __restrict__ src,
                           __nv_bfloat16* __restrict__ hi,
                           __nv_bfloat16* __restrict__ lo, int n)
{
    int i = blockIdx.x * blockDim.x + threadIdx.x;
    if (i >= n) return;
    int row = i >> 9;            // NKV*HD = 512
    int c   = i & 511;
    float f = src[(size_t)row * 3072 + 2560 + c];
    __nv_bfloat16 h = __float2bfloat16(f);
    float r = f - __bfloat162float(h);
    hi[i] = h;
    lo[i] = __float2bfloat16(r);
}

// ---------------------------------------------------------------------------
// Pipelined tensor-core split-bf16 GEMM (NT) — R14-exact (passing @1154)
// ---------------------------------------------------------------------------
#define GBM 128
#define GBN 128
#define GBK 32
#define LDS 40
#define TILE_B (GBM * LDS * 2)
#define OFF_AH 0
#define OFF_AL (TILE_B)
#define OFF_BH (2*TILE_B)
#define OFF_BL (3*TILE_B)
#define STAGE_B (4*TILE_B)
#define GEMM_SMEM (2*STAGE_B)

__global__ __launch_bounds__(256) void gemm_tc(
    const __nv_bfloat16* __restrict__ Ahg, const __nv_bfloat16* __restrict__ Alg,
    const __nv_bfloat16* __restrict__ Bhg, const __nv_bfloat16* __restrict__ Blg,
    float* __restrict__ C, int M, int N, int K)
{
    extern __shared__ char smem[];
    const uint32_t sb = smem_u32(smem);

    const int tid  = threadIdx.x;
    const int wid  = tid >> 5;
    const int lane = tid & 31;
    const int wm   = wid & 1;
    const int wn   = wid >> 1;

    const int brow = blockIdx.y * GBM;
    const int bcol = blockIdx.x * GBN;

    const uint32_t aoff = (uint32_t)((wm*64 + (lane & 15)) * (LDS*2) + (lane >> 4) * 16);
    const uint32_t boff = (uint32_t)((wn*32 + (lane & 7)) * (LDS*2) + ((lane >> 3) & 1) * 16);

    const int lr  = tid >> 2;
    const int lc8 = tid & 3;

    float acc[4][4][4];
    #pragma unroll
    for (int mi = 0; mi < 4; mi++)
        #pragma unroll
        for (int ni = 0; ni < 4; ni++)
            #pragma unroll
            for (int r = 0; r < 4; r++) acc[mi][ni][r] = 0.f;

    const int niter = K / GBK;

    auto load_stage = [&](int stage, int k0) {
        const uint32_t st = sb + stage * STAGE_B;
        #pragma unroll
        for (int i = 0; i < 2; i++) {
            int r = lr + i * 64;
            size_t ga = (size_t)(brow + r) * K + k0 + lc8 * 8;
            size_t gb = (size_t)(bcol + r) * K + k0 + lc8 * 8;
            uint32_t so = (uint32_t)(r * (LDS*2) + lc8 * 16);
            cp16(st + OFF_AH + so, Ahg + ga);
            cp16(st + OFF_AL + so, Alg + ga);
            cp16(st + OFF_BH + so, Bhg + gb);
            cp16(st + OFF_BL + so, Blg + gb);
        }
    };

    load_stage(0, 0);
    CP_COMMIT();

    for (int it = 0; it < niter; it++) {
        const int buf = it & 1;
        if (it + 1 < niter) {
            load_stage(buf ^ 1, (it + 1) * GBK);
            CP_COMMIT();
            CP_WAIT1();
        } else {
            CP_WAIT0();
        }
        __syncthreads();

        const uint32_t st = sb + buf * STAGE_B;
        #pragma unroll
        for (int kk = 0; kk < GBK; kk += 16) {
            const uint32_t kb = kk * 2;

            uint32_t ah[4][4], bh[4][2];
            #pragma unroll
            for (int mi = 0; mi < 4; mi++)
                ldsm_x4(ah[mi], st + OFF_AH + aoff + mi * 16 * (LDS*2) + kb);
            #pragma unroll
            for (int ni = 0; ni < 4; ni++)
                ldsm_x2(bh[ni], st + OFF_BH + boff + ni * 8 * (LDS*2) + kb);

            #pragma unroll
            for (int mi = 0; mi < 4; mi++)
                #pragma unroll
                for (int ni = 0; ni < 4; ni++)
                    mma16816(acc[mi][ni], ah[mi], bh[ni]);

            {
                uint32_t bl[4][2];
                #pragma unroll
                for (int ni = 0; ni < 4; ni++)
                    ldsm_x2(bl[ni], st + OFF_BL + boff + ni * 8 * (LDS*2) + kb);
                #pragma unroll
                for (int mi = 0; mi < 4; mi++)
                    #pragma unroll
                    for (int ni = 0; ni < 4; ni++)
                        mma16816(acc[mi][ni], ah[mi], bl[ni]);
            }
            {
                uint32_t al[4][4];
                #pragma unroll
                for (int mi = 0; mi < 4; mi++)
                    ldsm_x4(al[mi], st + OFF_AL + aoff + mi * 16 * (LDS*2) + kb);
                #pragma unroll
                for (int mi = 0; mi < 4; mi++)
                    #pragma unroll
                    for (int ni = 0; ni < 4; ni++)
                        mma16816(acc[mi][ni], al[mi], bh[ni]);
            }
        }
        __syncthreads();
    }

    const int er = lane >> 2;
    const int ec = (lane & 3) * 2;
    #pragma unroll
    for (int mi = 0; mi < 4; mi++) {
        #pragma unroll
        for (int ni = 0; ni < 4; ni++) {
            int row = brow + wm*64 + mi*16 + er;
            int col = bcol + wn*32 + ni*8 + ec;
            float2* p0 = (float2*)(C + (size_t)row * N + col);
            float2* p1 = (float2*)(C + (size_t)(row + 8) * N + col);
            *p0 = make_float2(acc[mi][ni][0], acc[mi][ni][1]);
            *p1 = make_float2(acc[mi][ni][2], acc[mi][ni][3]);
        }
    }
}

// ---------------------------------------------------------------------------
// RoPE fused with bf16 split. src has row stride srcStride; head h at col h*HD.
// ---------------------------------------------------------------------------
__global__ void rope_split(const float* __restrict__ src,
                           const float* __restrict__ cost,
                           const float* __restrict__ sint,
                           __nv_bfloat16* __restrict__ dh,
                           __nv_bfloat16* __restrict__ dl,
                           int rowsHeads, int nh, int srcStride, float scale)
{
    int idx = blockIdx.x * blockDim.x + threadIdx.x;
    int total = rowsHeads * 32;
    if (idx >= total) return;
    int d  = idx & 31;
    int rh = idx >> 5;
    int bt = rh / nh;
    int h  = rh - bt * nh;
    int t  = bt & (TT - 1);
    float c = cost[t * HD + d];
    float s = sint[t * HD + d];
    const float* base = src + (size_t)bt * srcStride + h * HD;
    float x1 = base[d];
    float x2 = base[d + 32];
    float y1 = fmaf(x1, c, -x2 * s) * scale;
    float y2 = fmaf(x2, c,  x1 * s) * scale;
    size_t o = (size_t)rh * HD;
    __nv_bfloat16 h1 = __float2bfloat16(y1);
    __nv_bfloat16 h2 = __float2bfloat16(y2);
    dh[o + d]      = h1;
    dh[o + d + 32] = h2;
    dl[o + d]      = __float2bfloat16(y1 - __bfloat162float(h1));
    dl[o + d + 32] = __float2bfloat16(y2 - __bfloat162float(h2));
}

// ---------------------------------------------------------------------------
// Flash attention v5: GQA-paired + LPT + 2-CTA occupancy.
// Q smem region is REUSED as KV stage 0 after fragments are extracted:
// smem = 2 stages of 36864 B only (73728 total -> 2 CTAs/SM).
// __launch_bounds__(256,2) caps regs at 128 so RF admits 2 CTAs.
// ---------------------------------------------------------------------------
#define ATQ 64
#define ATK 64
#define ASTRB  144       // 72 bf16 per row (64 data + 8 pad)
#define SQ_SZ    18432   // QH+QL per head (Q parked in stage area pre-loop)
#define SST_SZ   36864   // per stage: KH,KL,VH,VL each 9216
#define SK_H 0
#define SK_L 9216
#define SV_H 18432
#define SV_L 27648
#define ATTN_SMEM (2*SST_SZ)   // 73728 B -> 2 CTAs/SM

__global__ __launch_bounds__(256, 2) void attn_tc(
    const __nv_bfloat16* __restrict__ qsh, const __nv_bfloat16* __restrict__ qsl,
    const __nv_bfloat16* __restrict__ ksh, const __nv_bfloat16* __restrict__ ksl,
    const __nv_bfloat16* __restrict__ vsh, const __nv_bfloat16* __restrict__ vsl,
    __nv_bfloat16* __restrict__ Ohg, __nv_bfloat16* __restrict__ Olg)
{
    extern __shared__ char smem[];
    const uint32_t sb = smem_u32(smem);
    const int tid  = threadIdx.x;
    const int wid  = tid >> 5;        // 0..7
    const int lane = tid & 31;
    const int half = wid >> 2;        // 0/1 -> which q-head
    const int wih  = wid & 3;         // warp-in-half

    // LPT: heaviest (largest qt) CTAs launch first
    const int qt = (int)gridDim.x - 1 - (int)blockIdx.x;
    const int y  = blockIdx.y;        // b*(NKV*2) + kv*2 + ph
    const int b  = y >> 4;
    const int kv = (y >> 1) & 7;
    const int ph = y & 1;
    const int h  = kv * 4 + ph * 2 + half;
    const int q0 = qt * ATQ;
    const int ntiles = qt + 1;

    auto load_kv = [&](int stage, int k0) {
        const uint32_t st = sb + stage * SST_SZ;
        #pragma unroll
        for (int i = 0; i < 2; i++) {
            int idx = tid + i * 256;
            int r   = idx >> 3;
            int c8  = idx & 7;
            size_t g = ((size_t)(b * TT + k0 + r) * NKV + kv) * HD + c8 * 8;
            uint32_t so = (uint32_t)(r * ASTRB + c8 * 16);
            cp16(st + SK_H + so, ksh + g);
            cp16(st + SK_L + so, ksl + g);
            cp16(st + SV_H + so, vsh + g);
            cp16(st + SV_L + so, vsl + g);
        }
    };

    // ---- load both Q tiles into smem [0, 36864) (temporary parking) ----
    {
        const int tl = tid & 127;
        const uint32_t qbase = (uint32_t)((tid >> 7) * SQ_SZ);
        #pragma unroll
        for (int i = 0; i < 4; i++) {
            int idx = tl + i * 128;
            int r   = idx >> 3;
            int c8  = idx & 7;
            size_t g = ((size_t)(b * TT + q0 + r) * NH + h) * HD + c8 * 8;
            uint32_t so = qbase + (uint32_t)(r * ASTRB + c8 * 16);
            *(uint4*)(smem + so) = *(const uint4*)(qsh + g);
            *(uint4*)(smem + so + 9216) = *(const uint4*)(qsl + g);
        }
    }
    __syncthreads();   // Q visible to all warps

    // ---- per-warp Q fragments (held in registers for the whole kernel) ----
    uint32_t qh[4][4], ql[4][4];
    {
        uint32_t abase = (uint32_t)(half * SQ_SZ + (wih*16 + (lane & 15)) * ASTRB + (lane >> 4) * 16);
        #pragma unroll
        for (int ks = 0; ks < 4; ks++) {
            ldsm_x4(qh[ks], sb + abase + ks * 32);
            ldsm_x4(ql[ks], sb + abase + 9216 + ks * 32);
        }
    }
    __syncthreads();   // all warps done reading Q; smem may now be recycled

    // ---- start KV pipeline (stage 0 overwrites the Q parking area) ----
    load_kv(0, 0);
    CP_COMMIT();

    float o[8][4];
    #pragma unroll
    for (int dt = 0; dt < 8; dt++)
        #pragma unroll
        for (int r = 0; r < 4; r++) o[dt][r] = 0.f;
    float m0 = -1e30f, m1 = -1e30f, l0 = 0.f, l1 = 0.f;

    const uint32_t fb = (uint32_t)((lane & 15) * ASTRB + (lane >> 4) * 16);

    for (int kt = 0; kt < ntiles; kt++) {
        const int k0 = kt * ATK;
        if (kt + 1 < ntiles) {
            load_kv((kt + 1) & 1, k0 + ATK);
            CP_COMMIT();
            CP_WAIT1();
        } else {
            CP_WAIT0();
        }
        __syncthreads();

        const uint32_t st = sb + (kt & 1) * SST_SZ;

        // ---- S = Q K^T (split 3-pass, x4 B loads) ----
        float s[8][4];
        #pragma unroll
        for (int nt = 0; nt < 8; nt++)
            #pragma unroll
            for (int r = 0; r < 4; r++) s[nt][r] = 0.f;

        #pragma unroll
        for (int ks = 0; ks < 4; ks++) {
            #pragma unroll
            for (int np = 0; np < 4; np++) {
                uint32_t th[4], tl4[4];
                uint32_t ka = st + fb + np * (16 * ASTRB) + ks * 32;
                ldsm_x4(th,  SK_H + ka);
                ldsm_x4(tl4, SK_L + ka);
                uint32_t bh0[2] = {th[0], th[2]}, bh1[2] = {th[1], th[3]};
                uint32_t bl0[2] = {tl4[0], tl4[2]}, bl1[2] = {tl4[1], tl4[3]};
                mma16816(s[2*np],   qh[ks], bh0);
                mma16816(s[2*np],   qh[ks], bl0);
                mma16816(s[2*np],   ql[ks], bh0);
                mma16816(s[2*np+1], qh[ks], bh1);
                mma16816(s[2*np+1], qh[ks], bl1);
                mma16816(s[2*np+1], ql[ks], bh1);
            }
        }

        // ---- causal mask (diagonal tile only) ----
        const int row0 = q0 + wih * 16 + (lane >> 2);
        const int row1 = row0 + 8;
        if (kt == qt) {
            #pragma unroll
            for (int nt = 0; nt < 8; nt++) {
                int col = k0 + nt * 8 + (lane & 3) * 2;
                if (col     > row0) s[nt][0] = -1e30f;
                if (col + 1 > row0) s[nt][1] = -1e30f;
                if (col     > row1) s[nt][2] = -1e30f;
                if (col + 1 > row1) s[nt][3] = -1e30f;
            }
        }

        // ---- online softmax (exp2 domain) ----
        float mx0 = m0, mx1 = m1;
        #pragma unroll
        for (int nt = 0; nt < 8; nt++) {
            mx0 = fmaxf(mx0, fmaxf(s[nt][0], s[nt][1]));
            mx1 = fmaxf(mx1, fmaxf(s[nt][2], s[nt][3]));
        }
        mx0 = fmaxf(mx0, __shfl_xor_sync(0xFFFFFFFF, mx0, 1));
        mx0 = fmaxf(mx0, __shfl_xor_sync(0xFFFFFFFF, mx0, 2));
        mx1 = fmaxf(mx1, __shfl_xor_sync(0xFFFFFFFF, mx1, 1));
        mx1 = fmaxf(mx1, __shfl_xor_sync(0xFFFFFFFF, mx1, 2));

        float c0 = exp2f(m0 - mx0);
        float c1 = exp2f(m1 - mx1);
        m0 = mx0; m1 = mx1;
        l0 *= c0;  l1 *= c1;
        #pragma unroll
        for (int dt = 0; dt < 8; dt++) {
            o[dt][0] *= c0; o[dt][1] *= c0;
            o[dt][2] *= c1; o[dt][3] *= c1;
        }

        // ---- P = exp2(S - m), pack split A-fragments ----
        uint32_t pha[4][4], pla[4][4];
        float rs0 = 0.f, rs1 = 0.f;
        #pragma unroll
        for (int j = 0; j < 8; j++) {
            float p0 = exp2f(s[j][0] - m0);
            float p1 = exp2f(s[j][1] - m0);
            float p2 = exp2f(s[j][2] - m1);
            float p3 = exp2f(s[j][3] - m1);
            rs0 += p0 + p1;
            rs1 += p2 + p3;
            uint32_t hi01, lo01, hi23, lo23;
            split_pack(p0, p1, hi01, lo01);
            split_pack(p2, p3, hi23, lo23);
            int c = j >> 1;
            if ((j & 1) == 0) {
                pha[c][0] = hi01; pla[c][0] = lo01;
                pha[c][1] = hi23; pla[c][1] = lo23;
            } else {
                pha[c][2] = hi01; pla[c][2] = lo01;
                pha[c][3] = hi23; pla[c][3] = lo23;
            }
        }
        rs0 += __shfl_xor_sync(0xFFFFFFFF, rs0, 1);
        rs0 += __shfl_xor_sync(0xFFFFFFFF, rs0, 2);
        rs1 += __shfl_xor_sync(0xFFFFFFFF, rs1, 1);
        rs1 += __shfl_xor_sync(0xFFFFFFFF, rs1, 2);
        l0 += rs0;
        l1 += rs1;

        // ---- O += P V (x4 trans loads of row-major V) ----
        #pragma unroll
        for (int ks = 0; ks < 4; ks++) {
            #pragma unroll
            for (int dp = 0; dp < 4; dp++) {
                uint32_t vh4[4], vl4[4];
                uint32_t va = st + fb + ks * (16 * ASTRB) + dp * 32;
                ldsm_x4t(vh4, SV_H + va);
                ldsm_x4t(vl4, SV_L + va);
                uint32_t b0h[2] = {vh4[0], vh4[1]}, b1h[2] = {vh4[2], vh4[3]};
                uint32_t b0l[2] = {vl4[0], vl4[1]}, b1l[2] = {vl4[2], vl4[3]};
                mma16816(o[2*dp],   pha[ks], b0h);
                mma16816(o[2*dp],   pha[ks], b0l);
                mma16816(o[2*dp],   pla[ks], b0h);
                mma16816(o[2*dp+1], pha[ks], b1h);
                mma16816(o[2*dp+1], pha[ks], b1l);
                mma16816(o[2*dp+1], pla[ks], b1h);
            }
        }
        __syncthreads();
    }

    // ---- finalize & write split output ----
    const float i0 = 1.f / l0;
    const float i1 = 1.f / l1;
    const int row0 = q0 + wih * 16 + (lane >> 2);
    const int row1 = row0 + 8;
    const int colb = h * HD + (lane & 3) * 2;
    #pragma unroll
    for (int dt = 0; dt < 8; dt++) {
        int col = colb + dt * 8;
        uint32_t hi0, lo0, hi1, lo1;
        split_pack(o[dt][0] * i0, o[dt][1] * i0, hi0, lo0);
        split_pack(o[dt][2] * i1, o[dt][3] * i1, hi1, lo1);
        size_t g0 = (size_t)(b * TT + row0) * (NH * HD) + col;
        size_t g1 = (size_t)(b * TT + row1) * (NH * HD) + col;
        *(uint32_t*)(Ohg + g0) = hi0;
        *(uint32_t*)(Olg + g0) = lo0;
        *(uint32_t*)(Ohg + g1) = hi1;
        *(uint32_t*)(Olg + g1) = lo1;
    }
}

// ---------------------------------------------------------------------------
// Launch
// ---------------------------------------------------------------------------
extern "C" void kernel_launch(void* const* d_in, const int* in_sizes, int n_in,
                              void* d_out, int out_size)
{
    const float* x    = (const float*)d_in[0];
    const float* cosv = (const float*)d_in[1];
    const float* sinv = (const float*)d_in[2];
    const float* Wq   = (const float*)d_in[3];
    const float* Wk   = (const float*)d_in[4];
    const float* Wv   = (const float*)d_in[5];
    const float* Wo   = (const float*)d_in[6];
    float* out = (float*)d_out;

    float *qkv;
    cudaGetSymbolAddress((void**)&qkv, g_qkv);

    __nv_bfloat16 *xh, *xl, *wqkvh, *wqkvl, *woh, *wol, *ah, *al;
    __nv_bfloat16 *qsh, *qsl, *ksh, *ksl, *vsh, *vsl;
    cudaGetSymbolAddress((void**)&xh,    g_xh);     cudaGetSymbolAddress((void**)&xl,    g_xl);
    cudaGetSymbolAddress((void**)&wqkvh, g_wqkvh);  cudaGetSymbolAddress((void**)&wqkvl, g_wqkvl);
    cudaGetSymbolAddress((void**)&woh,   g_woh);    cudaGetSymbolAddress((void**)&wol,   g_wol);
    cudaGetSymbolAddress((void**)&ah,    g_ah);     cudaGetSymbolAddress((void**)&al,    g_al);
    cudaGetSymbolAddress((void**)&qsh,   g_qsh);    cudaGetSymbolAddress((void**)&qsl,   g_qsl);
    cudaGetSymbolAddress((void**)&ksh,   g_ksh);    cudaGetSymbolAddress((void**)&ksl,   g_ksl);
    cudaGetSymbolAddress((void**)&vsh,   g_vsh);    cudaGetSymbolAddress((void**)&vsl,   g_vsl);

    cudaFuncSetAttribute(gemm_tc, cudaFuncAttributeMaxDynamicSharedMemorySize, GEMM_SMEM);
    cudaFuncSetAttribute(attn_tc, cudaFuncAttributeMaxDynamicSharedMemorySize, ATTN_SMEM);

    // split conversions (inputs + weights; Wq|Wk|Wv concatenated along N)
    {
        int n;
        n = MROWS * DM;     cvt_split<<<(n+255)/256, 256>>>(x,  xh,  xl,  n);
        n = NH*HD * DM;     cvt_split<<<(n+255)/256, 256>>>(Wq, wqkvh, wqkvl, n);
        n = NKV*HD * DM;    cvt_split<<<(n+255)/256, 256>>>(Wk, wqkvh + (size_t)2048*DM, wqkvl + (size_t)2048*DM, n);
        n = NKV*HD * DM;    cvt_split<<<(n+255)/256, 256>>>(Wv, wqkvh + (size_t)2560*DM, wqkvl + (size_t)2560*DM, n);
        n = DM * NH*HD;     cvt_split<<<(n+255)/256, 256>>>(Wo, woh, wol, n);
    }

    // fused Q|K|V projection (N=3072)
    gemm_tc<<<dim3(3072/GBN, MROWS/GBM), 256, GEMM_SMEM>>>(xh, xl, wqkvh, wqkvl, qkv, MROWS, 3072, DM);

    // RoPE fused with split; q pre-scaled by (1/8)*log2(e) for exp2 softmax
    {
        int tq = MROWS * NH * 32;
        rope_split<<<(tq + 255)/256, 256>>>(qkv, cosv, sinv, qsh, qsl, MROWS*NH, NH, 3072, 0.18033688f);
        int tk = MROWS * NKV * 32;
        rope_split<<<(tk + 255)/256, 256>>>(qkv + 2048, cosv, sinv, ksh, ksl, MROWS*NKV, NKV, 3072, 1.0f);
        int nv = MROWS * NKV * HD;
        cvt_splitv<<<(nv + 255)/256, 256>>>(qkv, vsh, vsl, nv);
    }

    // tensor-core flash attention (GQA-paired, LPT, 2 CTAs/SM) -> split bf16 att
    attn_tc<<<dim3(TT/ATQ, BB*NKV*2), 256, ATTN_SMEM>>>(qsh, qsl, ksh, ksl, vsh, vsl, ah, al);

    // output projection
    gemm_tc<<<dim3(DM/GBN, MROWS/GBM), 256, GEMM_SMEM>>>(ah, al, woh, wol, out, MROWS, DM, DM);
}